// round 6
// baseline (speedup 1.0000x reference)
#include <cuda_runtime.h>
#include <cuda_fp16.h>
#include <math.h>
#include <stdint.h>

#define Bb   8
#define Tt   1024
#define DIMf 512
#define Hh   8
#define DKd  64
#define DHh  512
#define NHn  64
#define EPSf 1e-5f

// ---------------- scratch ---------------------------------------------------
__device__ float  g_qkv[Bb * 3 * DHh * Tt];
__device__ __half g_Wh [1536 * 512];
__device__ __half g_xh [Bb * Tt * DIMf];
__device__ __half g_Woh[512 * 512];
__device__ __half g_midh[Bb * DHh * Tt];
__device__ float  g_ctxp[8 * NHn * DKd * DKd];
__device__ float  g_S   [NHn * Tt];
__device__ float  g_P   [DKd * Tt];
__device__ float  g_M   [NHn * DKd];
__device__ float  g_invZ[NHn * DKd];
__device__ float  g_bns [DKd * 256];
__device__ float  g_bnq [DKd * 256];
__device__ float  g_sc  [DKd];
__device__ float  g_sh  [DKd];

// ---------------- PTX helpers -----------------------------------------------
__device__ __forceinline__ void cp16(void* smem, const void* gmem) {
    uint32_t s = (uint32_t)__cvta_generic_to_shared(smem);
    asm volatile("cp.async.cg.shared.global [%0], [%1], 16;\n" :: "r"(s), "l"(gmem));
}
__device__ __forceinline__ void cp16s(uint32_t s, const void* gmem) {
    asm volatile("cp.async.cg.shared.global [%0], [%1], 16;\n" :: "r"(s), "l"(gmem));
}
#define CP_COMMIT() asm volatile("cp.async.commit_group;\n")
#define CP_WAIT0()  asm volatile("cp.async.wait_group 0;\n")
#define CP_WAIT1()  asm volatile("cp.async.wait_group 1;\n")

__device__ __forceinline__ uint32_t smem_u32(const void* p) {
    uint32_t a;
    asm("{ .reg .u64 t; cvta.to.shared.u64 t, %1; cvt.u32.u64 %0, t; }" : "=r"(a) : "l"(p));
    return a;
}

__device__ __forceinline__ uint32_t f2tf(float x) {
    uint32_t r;
    asm("cvt.rna.tf32.f32 %0, %1;" : "=r"(r) : "f"(x));
    return r;
}

__device__ __forceinline__ void mma_tf32(float* c, const uint32_t* a, const uint32_t* b) {
    asm volatile(
        "mma.sync.aligned.m16n8k8.row.col.f32.tf32.tf32.f32 "
        "{%0,%1,%2,%3}, {%4,%5,%6,%7}, {%8,%9}, {%0,%1,%2,%3};\n"
        : "+f"(c[0]), "+f"(c[1]), "+f"(c[2]), "+f"(c[3])
        : "r"(a[0]), "r"(a[1]), "r"(a[2]), "r"(a[3]), "r"(b[0]), "r"(b[1]));
}

__device__ __forceinline__ void mma_f16(float* c, const uint32_t* a, const uint32_t* b) {
    asm volatile(
        "mma.sync.aligned.m16n8k16.row.col.f32.f16.f16.f32 "
        "{%0,%1,%2,%3}, {%4,%5,%6,%7}, {%8,%9}, {%0,%1,%2,%3};\n"
        : "+f"(c[0]), "+f"(c[1]), "+f"(c[2]), "+f"(c[3])
        : "r"(a[0]), "r"(a[1]), "r"(a[2]), "r"(a[3]), "r"(b[0]), "r"(b[1]));
}

__device__ __forceinline__ void ldsm_x4(uint32_t* r, uint32_t addr) {
    asm volatile("ldmatrix.sync.aligned.m8n8.x4.shared.b16 {%0,%1,%2,%3}, [%4];"
        : "=r"(r[0]), "=r"(r[1]), "=r"(r[2]), "=r"(r[3]) : "r"(addr));
}
__device__ __forceinline__ void ldsm_x4t(uint32_t* r, uint32_t addr) {
    asm volatile("ldmatrix.sync.aligned.m8n8.x4.trans.shared.b16 {%0,%1,%2,%3}, [%4];"
        : "=r"(r[0]), "=r"(r[1]), "=r"(r[2]), "=r"(r[3]) : "r"(addr));
}

// ---------------- convert W, x, Wout to fp16 --------------------------------
__global__ void k_round(const float* __restrict__ W, const float* __restrict__ x,
                        const float* __restrict__ Wo) {
    long i = (long)blockIdx.x * 256 + threadIdx.x;
    float4 v;
    __half* dst;
    long j;
    if (i < 196608) {
        v = ((const float4*)W)[i]; dst = g_Wh; j = i;
    } else if (i < 1245184) {
        j = i - 196608; v = ((const float4*)x)[j]; dst = g_xh;
    } else {
        j = i - 1245184; v = ((const float4*)Wo)[j]; dst = g_Woh;
    }
    __half2 p0 = __floats2half2_rn(v.x, v.y);
    __half2 p1 = __floats2half2_rn(v.z, v.w);
    uint2 u;
    u.x = *(const uint32_t*)&p0;
    u.y = *(const uint32_t*)&p1;
    ((uint2*)dst)[j] = u;
}

// ---------------- rel-pos band prefix ---------------------------------------
__global__ void k_prep(const float* __restrict__ relpos) {
    int gid = blockIdx.x * 256 + threadIdx.x;
    int d = gid >> 10, t = gid & 1023;
    int lo = 31 - t;    if (lo < 0)  lo = 0;
    int hi = 1054 - t;  if (hi > 62) hi = 62;
    float s = 0.f;
    for (int ri = lo; ri <= hi; ri++) s += relpos[ri * DKd + d];
    g_P[d * Tt + t] = s;
}

// ===================== GEMM1 (fp16 m16n8k16, TN) ===========================
__global__ __launch_bounds__(128, 2)
void k_gemm_qkv_h() {
    __shared__ __half As[2][128 * 40];
    __shared__ __half Bs[2][128 * 40];

    int tid = threadIdx.x, warp = tid >> 5, lane = tid & 31;
    int wm = (warp >> 1) * 64, wn = (warp & 1) * 64;
    int m0 = blockIdx.y * 128, n0 = blockIdx.x * 128;
    const __half* A  = g_Wh;
    const __half* Bm = g_xh + (long)blockIdx.z * Tt * DIMf;
    float*        C  = g_qkv + (long)blockIdx.z * 1536 * Tt;

    float acc[4][8][4];
    #pragma unroll
    for (int i = 0; i < 4; i++)
        #pragma unroll
        for (int j = 0; j < 8; j++)
            #pragma unroll
            for (int r = 0; r < 4; r++) acc[i][j][r] = 0.f;

    int g = lane >> 3, r8 = lane & 7;
    int a_off = ((g & 1) * 8 + r8) * 40 + (g >> 1) * 8;
    int b_off = ((g >> 1) * 8 + r8) * 40 + (g & 1) * 8;

    uint32_t sAs = smem_u32(As), sBs = smem_u32(Bs);

    const __half* arow = A  + (long)(m0 + tid) * 512;
    const __half* brow = Bm + (long)(n0 + tid) * 512;

    {
        uint32_t da = sAs + (uint32_t)(tid * 40) * 2;
        uint32_t db = sBs + (uint32_t)(tid * 40) * 2;
        #pragma unroll
        for (int q = 0; q < 4; q++) {
            cp16s(da + q * 16, arow + q * 8);
            cp16s(db + q * 16, brow + q * 8);
        }
        CP_COMMIT();
    }

    for (int kt = 0; kt < 16; kt++) {
        int buf = kt & 1;
        if (kt + 1 < 16) {
            uint32_t da = sAs + (uint32_t)((buf ^ 1) * 5120 + tid * 40) * 2;
            uint32_t db = sBs + (uint32_t)((buf ^ 1) * 5120 + tid * 40) * 2;
            const __half* ap = arow + (kt + 1) * 32;
            const __half* bp = brow + (kt + 1) * 32;
            #pragma unroll
            for (int q = 0; q < 4; q++) {
                cp16s(da + q * 16, ap + q * 8);
                cp16s(db + q * 16, bp + q * 8);
            }
            CP_COMMIT();
            CP_WAIT1();
        } else {
            CP_WAIT0();
        }
        __syncthreads();

        #pragma unroll
        for (int ks = 0; ks < 2; ks++) {
            uint32_t a[4][4], b[8][2];
            #pragma unroll
            for (int i = 0; i < 4; i++)
                ldsm_x4(a[i], sAs + (uint32_t)((buf * 5120 + (wm + i * 16) * 40 + ks * 16) + a_off) * 2);
            #pragma unroll
            for (int p = 0; p < 4; p++) {
                uint32_t r[4];
                ldsm_x4(r, sBs + (uint32_t)((buf * 5120 + (wn + p * 16) * 40 + ks * 16) + b_off) * 2);
                b[p * 2][0] = r[0]; b[p * 2][1] = r[1];
                b[p * 2 + 1][0] = r[2]; b[p * 2 + 1][1] = r[3];
            }
            #pragma unroll
            for (int i = 0; i < 4; i++)
                #pragma unroll
                for (int j = 0; j < 8; j++)
                    mma_f16(acc[i][j], a[i], b[j]);
        }
        __syncthreads();
    }

    int lrow = lane >> 2;
    #pragma unroll
    for (int i = 0; i < 4; i++) {
        #pragma unroll
        for (int j = 0; j < 8; j++) {
            int m = m0 + wm + i * 16 + lrow;
            int n = n0 + wn + j * 8 + (lane & 3) * 2;
            *(float2*)&C[(long)m * Tt + n]       = make_float2(acc[i][j][0], acc[i][j][1]);
            *(float2*)&C[(long)(m + 8) * Tt + n] = make_float2(acc[i][j][2], acc[i][j][3]);
        }
    }
}

// ===================== GEMM2 (fp16 m16n8k16, NN via trans) =================
__global__ __launch_bounds__(128, 2)
void k_gemm_out_h(const float* __restrict__ bias, float* __restrict__ out) {
    __shared__ __half As[2][128 * 40];
    __shared__ __half Bs[2][32 * 136];

    int tid = threadIdx.x, warp = tid >> 5, lane = tid & 31;
    int wm = (warp >> 1) * 64, wn = (warp & 1) * 64;
    int m0 = blockIdx.y * 128, n0 = blockIdx.x * 128;
    const __half* A  = g_Woh;
    const __half* Bm = g_midh + (long)blockIdx.z * 512 * Tt;
    float*        C  = out    + (long)blockIdx.z * 512 * Tt;

    float acc[4][8][4];
    #pragma unroll
    for (int i = 0; i < 4; i++)
        #pragma unroll
        for (int j = 0; j < 8; j++)
            #pragma unroll
            for (int r = 0; r < 4; r++) acc[i][j][r] = 0.f;

    int g = lane >> 3, r8 = lane & 7;
    int a_off  = ((g & 1) * 8 + r8) * 40 + (g >> 1) * 8;
    int bt_off = ((g & 1) * 8 + r8) * 136 + (g >> 1) * 8;

    uint32_t sAs = smem_u32(As), sBs = smem_u32(Bs);

    const __half* arow = A + (long)(m0 + tid) * 512;
    int brw = tid >> 2, bq = tid & 3;
    const __half* brow = Bm + (long)brw * Tt + n0;

    {
        uint32_t da = sAs + (uint32_t)(tid * 40) * 2;
        #pragma unroll
        for (int q = 0; q < 4; q++) cp16s(da + q * 16, arow + q * 8);
        uint32_t db = sBs + (uint32_t)(brw * 136) * 2;
        #pragma unroll
        for (int s = 0; s < 4; s++) {
            int qq = bq * 4 + s;
            cp16s(db + qq * 16, brow + qq * 8);
        }
        CP_COMMIT();
    }

    for (int kt = 0; kt < 16; kt++) {
        int buf = kt & 1;
        if (kt + 1 < 16) {
            int k0 = (kt + 1) * 32;
            uint32_t da = sAs + (uint32_t)((buf ^ 1) * 5120 + tid * 40) * 2;
            const __half* ap = arow + k0;
            #pragma unroll
            for (int q = 0; q < 4; q++) cp16s(da + q * 16, ap + q * 8);
            uint32_t db = sBs + (uint32_t)((buf ^ 1) * 4352 + brw * 136) * 2;
            const __half* bp = brow + (long)k0 * Tt;
            #pragma unroll
            for (int s = 0; s < 4; s++) {
                int qq = bq * 4 + s;
                cp16s(db + qq * 16, bp + qq * 8);
            }
            CP_COMMIT();
            CP_WAIT1();
        } else {
            CP_WAIT0();
        }
        __syncthreads();

        #pragma unroll
        for (int ks = 0; ks < 2; ks++) {
            uint32_t a[4][4], b[8][2];
            #pragma unroll
            for (int i = 0; i < 4; i++)
                ldsm_x4(a[i], sAs + (uint32_t)((buf * 5120 + (wm + i * 16) * 40 + ks * 16) + a_off) * 2);
            #pragma unroll
            for (int p = 0; p < 4; p++) {
                uint32_t r[4];
                ldsm_x4t(r, sBs + (uint32_t)((buf * 4352 + (ks * 16) * 136 + wn + p * 16) + bt_off) * 2);
                b[p * 2][0] = r[0]; b[p * 2][1] = r[1];
                b[p * 2 + 1][0] = r[2]; b[p * 2 + 1][1] = r[3];
            }
            #pragma unroll
            for (int i = 0; i < 4; i++)
                #pragma unroll
                for (int j = 0; j < 8; j++)
                    mma_f16(acc[i][j], a[i], b[j]);
        }
        __syncthreads();
    }

    int lrow = lane >> 2;
    #pragma unroll
    for (int i = 0; i < 4; i++) {
        #pragma unroll
        for (int j = 0; j < 8; j++) {
            int m = m0 + wm + i * 16 + lrow;
            int n = n0 + wn + j * 8 + (lane & 3) * 2;
            float bv0 = bias[m], bv1 = bias[m + 8];
            *(float2*)&C[(long)m * Tt + n] =
                make_float2(acc[i][j][0] + bv0, acc[i][j][1] + bv0);
            *(float2*)&C[(long)(m + 8) * Tt + n] =
                make_float2(acc[i][j][2] + bv1, acc[i][j][3] + bv1);
        }
    }
}

// ---------------- per-row softmax stats (max, 1/Z), 1 block per row ---------
__global__ void k_mz() {
    int row = blockIdx.x;               // 0..4095 == b*512 + r,  == n*64+d
    int b = row >> 9, r = row & 511;
    const float* src = g_qkv + ((long)b * 1536 + 512 + r) * Tt;
    int tid = threadIdx.x;

    float4 x = ((const float4*)src)[tid];
    float m = fmaxf(fmaxf(x.x, x.y), fmaxf(x.z, x.w));
    #pragma unroll
    for (int o = 16; o; o >>= 1) m = fmaxf(m, __shfl_xor_sync(0xffffffffu, m, o));
    __shared__ float sm[8], ssum[8];
    if ((tid & 31) == 0) sm[tid >> 5] = m;
    __syncthreads();
    float M = sm[0];
    #pragma unroll
    for (int i = 1; i < 8; i++) M = fmaxf(M, sm[i]);

    float s = exp2f((x.x - M) * 1.44269504f) + exp2f((x.y - M) * 1.44269504f)
            + exp2f((x.z - M) * 1.44269504f) + exp2f((x.w - M) * 1.44269504f);
    #pragma unroll
    for (int o = 16; o; o >>= 1) s += __shfl_xor_sync(0xffffffffu, s, o);
    if ((tid & 31) == 0) ssum[tid >> 5] = s;
    __syncthreads();
    if (tid == 0) {
        float S = 0.f;
        #pragma unroll
        for (int i = 0; i < 8; i++) S += ssum[i];
        g_M[row] = M;
        g_invZ[row] = 1.f / S;
    }
}

// ---------------- S + BN partials (independent of ctx) -----------------------
// grid (4, 64), 256 threads: S[n, t0+tid]; then BN partials per e
__global__ __launch_bounds__(256)
void k_Sbn() {
    int tc = blockIdx.x, n = blockIdx.y;
    int t0 = tc * 256;
    int tid = threadIdx.x, warp = tid >> 5, lane = tid & 31;
    int b = n >> 3, h = n & 7;
    const float* Q = g_qkv + ((long)b * 1536 + h * 64) * Tt;
    const float* V = g_qkv + ((long)b * 1536 + 1024 + h * 64) * Tt;

    __shared__ float sS[256];
    int t = t0 + tid;
    float S = 0.f;
    #pragma unroll
    for (int d = 0; d < 64; d++) S += Q[(long)d * Tt + t] * g_P[d * Tt + t];
    g_S[n * Tt + t] = S;
    sS[tid] = S;
    __syncthreads();

    // warp w handles e = w*8 .. w*8+7
    #pragma unroll
    for (int i = 0; i < 8; i++) {
        int e = warp * 8 + i;
        const float* vrow = V + (long)e * Tt + t0;
        float sum = 0.f, sq = 0.f;
        #pragma unroll
        for (int it = 0; it < 8; it++) {
            int tt = it * 32 + lane;
            float r = vrow[tt] * sS[tt];
            sum += r; sq += r * r;
        }
        #pragma unroll
        for (int o = 16; o; o >>= 1) {
            sum += __shfl_xor_sync(0xffffffffu, sum, o);
            sq  += __shfl_xor_sync(0xffffffffu, sq,  o);
        }
        if (lane == 0) {
            g_bns[e * 256 + n * 4 + tc] = sum;
            g_bnq[e * 256 + n * 4 + tc] = sq;
        }
    }
}

__global__ void k_bnred(const float* __restrict__ gamma, const float* __restrict__ beta) {
    int tid = threadIdx.x;              // 256
    int e = tid >> 2, p = tid & 3;
    float s = 0.f, q = 0.f;
    #pragma unroll
    for (int j = 0; j < 64; j++) {
        s += g_bns[e * 256 + p * 64 + j];
        q += g_bnq[e * 256 + p * 64 + j];
    }
    s += __shfl_down_sync(0xffffffffu, s, 2, 4);
    q += __shfl_down_sync(0xffffffffu, q, 2, 4);
    s += __shfl_down_sync(0xffffffffu, s, 1, 4);
    q += __shfl_down_sync(0xffffffffu, q, 1, 4);
    if (p == 0) {
        const float cnt = (float)(NHn * Tt);
        float mu  = s / cnt;
        float var = q / cnt - mu * mu;
        float sc  = gamma[e] * rsqrtf(var + EPSf);
        g_sc[e] = sc;
        g_sh[e] = beta[e] - mu * sc;
    }
}

// ---------------- ctx via tf32 mma with fused exp, 8 slices ------------------
__global__ __launch_bounds__(128)
void k_ctx_mma() {
    int s = blockIdx.x, n = blockIdx.y;          // s 0..7
    int b = n >> 3, h = n & 7;
    const float* Kraw = g_qkv + ((long)b * 1536 + 512  + h * 64) * Tt;
    const float* Vp   = g_qkv + ((long)b * 1536 + 1024 + h * 64) * Tt;

    __shared__ float Ks[64 * 68];
    __shared__ float Vs[64 * 68];
    __shared__ float sM[64], sZ[64];

    int tid = threadIdx.x;
    if (tid < 64) { sM[tid] = g_M[n * 64 + tid]; sZ[tid] = g_invZ[n * 64 + tid]; }

    int warp = tid >> 5, lane = tid & 31;
    int wm = (warp >> 1) * 32, wn = (warp & 1) * 32;
    int lrow = lane >> 2, lcol = lane & 3;
    int tv = (tid & 15) * 4, dl = tid >> 4;

    float acc[2][4][4];
    #pragma unroll
    for (int i = 0; i < 2; i++)
        #pragma unroll
        for (int j = 0; j < 4; j++)
            #pragma unroll
            for (int r = 0; r < 4; r++) acc[i][j][r] = 0.f;

    __syncthreads();

    for (int c = 0; c < 2; c++) {
        int t0 = s * 128 + c * 64;
        #pragma unroll
        for (int dd = 0; dd < 8; dd++) {
            int e = dd * 8 + dl;
            cp16(&Vs[e * 68 + tv], &Vp[(long)e * Tt + t0 + tv]);
        }
        CP_COMMIT();
        #pragma unroll
        for (int dd = 0; dd < 8; dd++) {
            int d = dd * 8 + dl;
            float4 kv = *(const float4*)&Kraw[(long)d * Tt + t0 + tv];
            float M = sM[d], iz = sZ[d];
            float4 o;
            o.x = exp2f((kv.x - M) * 1.44269504f) * iz;
            o.y = exp2f((kv.y - M) * 1.44269504f) * iz;
            o.z = exp2f((kv.z - M) * 1.44269504f) * iz;
            o.w = exp2f((kv.w - M) * 1.44269504f) * iz;
            *(float4*)&Ks[d * 68 + tv] = o;
        }
        CP_WAIT0();
        __syncthreads();

        #pragma unroll
        for (int k8 = 0; k8 < 8; k8++) {
            int kb = k8 * 8 + lcol;
            uint32_t a[2][4], bf[4][2];
            #pragma unroll
            for (int i = 0; i < 2; i++) {
                int m = wm + i * 16 + lrow;
                a[i][0] = f2tf(Ks[m * 68 + kb]);
                a[i][1] = f2tf(Ks[(m + 8) * 68 + kb]);
                a[i][2] = f2tf(Ks[m * 68 + kb + 4]);
                a[i][3] = f2tf(Ks[(m + 8) * 68 + kb + 4]);
            }
            #pragma unroll
            for (int j = 0; j < 4; j++) {
                int e = wn + j * 8 + lrow;
                bf[j][0] = f2tf(Vs[e * 68 + kb]);
                bf[j][1] = f2tf(Vs[e * 68 + kb + 4]);
            }
            #pragma unroll
            for (int i = 0; i < 2; i++)
                #pragma unroll
                for (int j = 0; j < 4; j++)
                    mma_tf32(acc[i][j], a[i], bf[j]);
        }
        __syncthreads();
    }

    float* dst = g_ctxp + ((long)(s * NHn + n)) * 4096;
    #pragma unroll
    for (int i = 0; i < 2; i++) {
        #pragma unroll
        for (int j = 0; j < 4; j++) {
            int d = wm + i * 16 + lrow;
            int e = wn + j * 8 + (lane & 3) * 2;
            *(float2*)&dst[d * 64 + e]       = make_float2(acc[i][j][0], acc[i][j][1]);
            *(float2*)&dst[(d + 8) * 64 + e] = make_float2(acc[i][j][2], acc[i][j][3]);
        }
    }
}

// ---------------- content + full epilogue -> fp16 midh ----------------------
__global__ __launch_bounds__(256)
void k_content() {
    int n = blockIdx.y;
    int t = blockIdx.x * 256 + threadIdx.x;
    int b = n >> 3, h = n & 7;
    const float* Q = g_qkv + ((long)b * 1536 + h * 64) * Tt;
    const float* V = g_qkv + ((long)b * 1536 + 1024 + h * 64) * Tt;

    __shared__ float cs[4096];
    __shared__ float ssc[64], ssh[64];
    if (threadIdx.x < 64) {
        ssc[threadIdx.x] = g_sc[threadIdx.x];
        ssh[threadIdx.x] = g_sh[threadIdx.x];
    }
    {
        for (int i = threadIdx.x; i < 1024; i += 256) {
            float4 a = ((const float4*)(g_ctxp + (long)n * 4096))[i];
            #pragma unroll
            for (int p = 1; p < 8; p++) {
                float4 x = ((const float4*)(g_ctxp + (long)(p * NHn + n) * 4096))[i];
                a.x += x.x; a.y += x.y; a.z += x.z; a.w += x.w;
            }
            ((float4*)cs)[i] = a;
        }
    }
    __syncthreads();

    float q[64];
    #pragma unroll
    for (int d = 0; d < 64; d++) q[d] = Q[(long)d * Tt + t];

    float S = g_S[n * Tt + t];

    __half* dst = g_midh + ((long)b * 512 + h * 64) * Tt + t;
    #pragma unroll
    for (int e0 = 0; e0 < 64; e0 += 4) {
        float4 a = make_float4(0.f, 0.f, 0.f, 0.f);
        #pragma unroll
        for (int d = 0; d < 64; d++) {
            float4 c = *(const float4*)&cs[d * 64 + e0];
            a.x += c.x * q[d]; a.y += c.y * q[d];
            a.z += c.z * q[d]; a.w += c.w * q[d];
        }
        // BN(v*S) epilogue
        float v0 = V[(long)(e0 + 0) * Tt + t];
        float v1 = V[(long)(e0 + 1) * Tt + t];
        float v2 = V[(long)(e0 + 2) * Tt + t];
        float v3 = V[(long)(e0 + 3) * Tt + t];
        a.x += v0 * S * ssc[e0 + 0] + ssh[e0 + 0];
        a.y += v1 * S * ssc[e0 + 1] + ssh[e0 + 1];
        a.z += v2 * S * ssc[e0 + 2] + ssh[e0 + 2];
        a.w += v3 * S * ssc[e0 + 3] + ssh[e0 + 3];
        dst[(long)(e0 + 0) * Tt] = __float2half_rn(a.x);
        dst[(long)(e0 + 1) * Tt] = __float2half_rn(a.y);
        dst[(long)(e0 + 2) * Tt] = __float2half_rn(a.z);
        dst[(long)(e0 + 3) * Tt] = __float2half_rn(a.w);
    }
}

// ---------------- launcher ---------------------------------------------------
extern "C" void kernel_launch(void* const* d_in, const int* in_sizes, int n_in,
                              void* d_out, int out_size) {
    const float* x      = (const float*)d_in[0];
    const float* Wqkv   = (const float*)d_in[1];
    const float* Wout   = (const float*)d_in[2];
    const float* bout   = (const float*)d_in[3];
    const float* relpos = (const float*)d_in[4];
    const float* gamma  = (const float*)d_in[5];
    const float* beta   = (const float*)d_in[6];
    float* out = (float*)d_out;

    k_prep<<<256, 256>>>(relpos);
    k_round<<<5120, 256>>>(Wqkv, x, Wout);
    k_gemm_qkv_h<<<dim3(8, 12, 8), 128>>>();
    k_mz<<<4096, 256>>>();
    k_Sbn<<<dim3(4, 64), 256>>>();
    k_bnred<<<1, 256>>>(gamma, beta);
    k_ctx_mma<<<dim3(8, 64), 128>>>();
    k_content<<<dim3(4, 64), 256>>>();
    k_gemm_out_h<<<dim3(8, 4, 8), 128>>>(bout, out);
}